// round 15
// baseline (speedup 1.0000x reference)
#include <cuda_runtime.h>
#include <cuda_fp16.h>
#include <cstdint>

#define NN 50000
#define EE 800000
#define GG 1024
#define DD 128
#define HH 4
#define LL 3
#define NODE_DIM 78
#define HID 1024

// ---------------- scratch (device globals; no allocation allowed) ----------
__device__ float g_h[NN * DD];
__device__ __half g_hp[(size_t)NN * HH * DD];   // 51.2 MB (fp16); also x-pad scratch
__device__ float g_hn[NN * DD];
__device__ float g_as[NN * HH];
__device__ float g_ad[NN * HH];
__device__ int   g_rowptr[NN + 1];
__device__ int   g_cnt[NN];
__device__ int   g_cur[NN];
__device__ int   g_col[EE];
__device__ int   g_bsum[64];
__device__ int   g_gmax[LL * HH];
__device__ float g_pooled[GG * DD];
__device__ int   g_gcnt[GG];
__device__ int   g_goff[GG + 1];
__device__ float g_hidden[GG * HID];
// transposed / K-padded weights: W1T, W2T, lin_wT[3][512][128], gW1T[1024][128]
__device__ float g_wT[2 * 128 * 128 + 3 * 512 * 128 + 1024 * 128];

__device__ __forceinline__ int f2ord(float f) {
    int i = __float_as_int(f);
    return (i >= 0) ? i : i ^ 0x7FFFFFFF;
}
__device__ __forceinline__ float ord2f(int i) {
    return __int_as_float((i >= 0) ? i : i ^ 0x7FFFFFFF);
}
__device__ __forceinline__ float leaky02(float e) { return e > 0.f ? e : 0.2f * e; }

// ---------------- init: zero cnt/cur/gcnt, set gmax sentinels ---------------
__global__ void init_misc_kernel(int* cnt, int* cur, int* gcnt, int* gmax) {
    int i = blockIdx.x * blockDim.x + threadIdx.x;
    if (i < NN) { cnt[i] = 0; cur[i] = 0; }
    if (i < GG) gcnt[i] = 0;
    if (i < LL * HH) gmax[i] = f2ord(-3.0e38f);
}

// ---------------- pad x [NN,78] -> xp [NN,128] fp32 -------------------------
__global__ void pad_x_kernel(const float* __restrict__ x, float* __restrict__ xp) {
    int idx = blockIdx.x * blockDim.x + threadIdx.x;
    if (idx >= NN * 32) return;
    int row = idx >> 5;
    int q = idx & 31;
    int c = q * 4;
    const float* xr = x + (size_t)row * NODE_DIM;
    float4 v = make_float4(0.f, 0.f, 0.f, 0.f);
    if (c + 3 < NODE_DIM) {
        v.x = xr[c]; v.y = xr[c + 1]; v.z = xr[c + 2]; v.w = xr[c + 3];
    } else {
        if (c < NODE_DIM) v.x = xr[c];
        if (c + 1 < NODE_DIM) v.y = xr[c + 1];
        if (c + 2 < NODE_DIM) v.z = xr[c + 2];
        if (c + 3 < NODE_DIM) v.w = xr[c + 3];
    }
    *(float4*)(xp + (size_t)row * 128 + c) = v;
}

// ---------------- batched transpose + pad-K of all 6 weights ---------------
__global__ void transpose_all_kernel(const float* __restrict__ W1,
                                     const float* __restrict__ W2,
                                     const float* __restrict__ lin_w,
                                     const float* __restrict__ gW1,
                                     float* __restrict__ w1T,
                                     float* __restrict__ w2T,
                                     float* __restrict__ linT,
                                     float* __restrict__ gW1T) {
    __shared__ float t[32][33];
    const int job = blockIdx.z;
    const float* src; float* dst; int K, Nsrc;
    switch (job) {
        case 0: src = W1; dst = w1T; K = NODE_DIM; Nsrc = 128; break;
        case 1: src = W2; dst = w2T; K = 128; Nsrc = 128; break;
        case 5: src = gW1; dst = gW1T; K = 128; Nsrc = 1024; break;
        default:
            src = lin_w + (size_t)(job - 2) * 128 * 512;
            dst = linT + (size_t)(job - 2) * 512 * 128;
            K = 128; Nsrc = 512; break;
    }
    int n0 = blockIdx.x * 32, k0 = blockIdx.y * 32;
    if (n0 >= Nsrc) return;
    int tx = threadIdx.x, ty = threadIdx.y;
#pragma unroll
    for (int i = 0; i < 32; i += 8) {
        int k = k0 + ty + i, n = n0 + tx;
        t[ty + i][tx] = (k < K && n < Nsrc) ? src[(size_t)k * Nsrc + n] : 0.f;
    }
    __syncthreads();
#pragma unroll
    for (int i = 0; i < 32; i += 8) {
        int n = n0 + ty + i, k = k0 + tx;
        if (n < Nsrc) dst[(size_t)n * 128 + k] = t[tx][ty + i];
    }
}

// ---------------- fp16 mma.sync GEMM, tile 128x128, K=128, fused epilogue --
// 256 threads = 8 warps in 4x2 grid (each warp 32 rows x 64 cols).
// SMEM ~71 KB -> 2 CTAs/SM for latency overlap.
#define HS 136
#define BMROWS 128
#define GTHREADS 256
#define A_BYTES (BMROWS * HS * 2)
#define B_BYTES (128 * HS * 2)
#define ASBUF_OFF (A_BYTES + B_BYTES)
#define SM_BYTES (ASBUF_OFF + 2 * BMROWS * 4)

__global__ void __launch_bounds__(GTHREADS)
h16_gemm_fused(const float* __restrict__ A, int M,
               const float* __restrict__ Bt,     // [nChunks*128][128] pre-transposed
               const float* __restrict__ bias,   // global-col indexed or null
               void* __restrict__ C, int c_stride,
               int relu, int half_out,
               const float* __restrict__ attS,   // global-col indexed or null
               const float* __restrict__ attD,
               float* __restrict__ asOut, float* __restrict__ adOut,
               int* __restrict__ gmaxOut)
{
    extern __shared__ char smc[];
    __half* As = (__half*)smc;
    __half* Bs = (__half*)(smc + A_BYTES);
    float* asbuf = (float*)(smc + ASBUF_OFF);
    float* adbuf = asbuf + BMROWS;

    const int tid = threadIdx.x;
    const int wid = tid >> 5, lane = tid & 31;
    const int grp = lane >> 2, tig = lane & 3;
    const int wm = wid & 3, wn = wid >> 2;      // 4 x 2 warp grid
    const int nc = blockIdx.x;
    const int m0 = blockIdx.y * BMROWS;
    const int rows = min(BMROWS, M - m0);
    const int colg0 = nc * 128;

    // ---- load tiles to SMEM (convert fp32 -> fp16); K is always 128 ----
    {
        const float4* src = (const float4*)(A + (size_t)m0 * 128);
        for (int idx = tid; idx < BMROWS * 32; idx += GTHREADS) {
            int row = idx >> 5, q = idx & 31;
            float4 v = make_float4(0.f, 0.f, 0.f, 0.f);
            if (row < rows) v = src[row * 32 + q];
            __half2 p0 = __floats2half2_rn(v.x, v.y);
            __half2 p1 = __floats2half2_rn(v.z, v.w);
            uint2 u;
            u.x = *(uint32_t*)&p0;
            u.y = *(uint32_t*)&p1;
            *(uint2*)(As + row * HS + q * 4) = u;
        }
    }
    {
        const float4* src = (const float4*)(Bt + (size_t)nc * 128 * 128);
        for (int idx = tid; idx < 128 * 32; idx += GTHREADS) {
            int row = idx >> 5, q = idx & 31;
            float4 v = src[row * 32 + q];
            __half2 p0 = __floats2half2_rn(v.x, v.y);
            __half2 p1 = __floats2half2_rn(v.z, v.w);
            uint2 u;
            u.x = *(uint32_t*)&p0;
            u.y = *(uint32_t*)&p1;
            *(uint2*)(Bs + row * HS + q * 4) = u;
        }
    }
    if (tid < BMROWS) { asbuf[tid] = 0.f; adbuf[tid] = 0.f; }
    __syncthreads();

    // ---- main MMA loop: 8 k-steps of m16n8k16 ----
    float acc[2][8][4];
#pragma unroll
    for (int mi = 0; mi < 2; mi++)
#pragma unroll
        for (int ni = 0; ni < 8; ni++)
#pragma unroll
            for (int q = 0; q < 4; q++) acc[mi][ni][q] = 0.f;

#pragma unroll
    for (int ks = 0; ks < 8; ks++) {
        const int k0 = ks * 16;
        uint32_t a[2][4];
#pragma unroll
        for (int mi = 0; mi < 2; mi++) {
            int rb = wm * 32 + mi * 16 + grp;
            a[mi][0] = *(const uint32_t*)(As + rb * HS + k0 + 2 * tig);
            a[mi][1] = *(const uint32_t*)(As + (rb + 8) * HS + k0 + 2 * tig);
            a[mi][2] = *(const uint32_t*)(As + rb * HS + k0 + 2 * tig + 8);
            a[mi][3] = *(const uint32_t*)(As + (rb + 8) * HS + k0 + 2 * tig + 8);
        }
        uint32_t b[8][2];
#pragma unroll
        for (int ni = 0; ni < 8; ni++) {
            int cb = wn * 64 + ni * 8 + grp;
            b[ni][0] = *(const uint32_t*)(Bs + cb * HS + k0 + 2 * tig);
            b[ni][1] = *(const uint32_t*)(Bs + cb * HS + k0 + 2 * tig + 8);
        }
#pragma unroll
        for (int mi = 0; mi < 2; mi++)
#pragma unroll
            for (int ni = 0; ni < 8; ni++) {
                asm volatile(
                    "mma.sync.aligned.m16n8k16.row.col.f32.f16.f16.f32 "
                    "{%0,%1,%2,%3}, {%4,%5,%6,%7}, {%8,%9}, {%0,%1,%2,%3};"
                    : "+f"(acc[mi][ni][0]), "+f"(acc[mi][ni][1]),
                      "+f"(acc[mi][ni][2]), "+f"(acc[mi][ni][3])
                    : "r"(a[mi][0]), "r"(a[mi][1]), "r"(a[mi][2]), "r"(a[mi][3]),
                      "r"(b[ni][0]), "r"(b[ni][1]));
            }
    }

    // ---- epilogue: bias/relu/store + fused attention dots ----
#pragma unroll
    for (int mi = 0; mi < 2; mi++) {
        const int r0 = wm * 32 + mi * 16 + grp;
        const int r1 = r0 + 8;
        const int gm0 = m0 + r0, gm1 = m0 + r1;
        float aS0 = 0.f, aD0 = 0.f, aS1 = 0.f, aD1 = 0.f;
#pragma unroll
        for (int ni = 0; ni < 8; ni++) {
            const int col = wn * 64 + ni * 8 + tig * 2;
            const int cg = colg0 + col;
            float v0 = acc[mi][ni][0], v1 = acc[mi][ni][1];
            float v2 = acc[mi][ni][2], v3 = acc[mi][ni][3];
            if (bias) {
                float b0 = bias[cg], b1 = bias[cg + 1];
                v0 += b0; v1 += b1; v2 += b0; v3 += b1;
            }
            if (relu) {
                v0 = fmaxf(v0, 0.f); v1 = fmaxf(v1, 0.f);
                v2 = fmaxf(v2, 0.f); v3 = fmaxf(v3, 0.f);
            }
            if (attS) {
                float s0 = attS[cg], s1 = attS[cg + 1];
                float d0 = attD[cg], d1 = attD[cg + 1];
                aS0 += v0 * s0 + v1 * s1;
                aD0 += v0 * d0 + v1 * d1;
                aS1 += v2 * s0 + v3 * s1;
                aD1 += v2 * d0 + v3 * d1;
            }
            if (half_out) {
                __half* Ch = (__half*)C;
                if (gm0 < M)
                    *(__half2*)(Ch + (size_t)gm0 * c_stride + cg) = __floats2half2_rn(v0, v1);
                if (gm1 < M)
                    *(__half2*)(Ch + (size_t)gm1 * c_stride + cg) = __floats2half2_rn(v2, v3);
            } else {
                float* Cf = (float*)C;
                if (gm0 < M) *(float2*)(Cf + (size_t)gm0 * c_stride + cg) = make_float2(v0, v1);
                if (gm1 < M) *(float2*)(Cf + (size_t)gm1 * c_stride + cg) = make_float2(v2, v3);
            }
        }
        if (attS) {
#pragma unroll
            for (int off = 1; off < 4; off <<= 1) {
                aS0 += __shfl_xor_sync(0xffffffffu, aS0, off);
                aD0 += __shfl_xor_sync(0xffffffffu, aD0, off);
                aS1 += __shfl_xor_sync(0xffffffffu, aS1, off);
                aD1 += __shfl_xor_sync(0xffffffffu, aD1, off);
            }
            if (tig == 0) {
                atomicAdd(&asbuf[r0], aS0);
                atomicAdd(&adbuf[r0], aD0);
                atomicAdd(&asbuf[r1], aS1);
                atomicAdd(&adbuf[r1], aD1);
            }
        }
    }
    if (attS) {
        __syncthreads();
        if (tid < BMROWS && m0 + tid < M) {
            asOut[(m0 + tid) * HH + nc] = asbuf[tid];
            adOut[(m0 + tid) * HH + nc] = adbuf[tid];
        }
        // fused per-head global max bound (last warp)
        if (wid == 7) {
            float m = -3.0e38f;
            for (int i = lane; i < rows; i += 32) m = fmaxf(m, asbuf[i]);
#pragma unroll
            for (int off = 16; off; off >>= 1)
                m = fmaxf(m, __shfl_xor_sync(0xffffffffu, m, off));
            if (lane == 0) atomicMax(gmaxOut + nc, f2ord(m));
        }
    }
}

// ---------------- SIMT SGEMM (FC2 only: K=1024) ------------------------------
template <int BM, int BN, int BK, int TM, int TN>
__global__ void __launch_bounds__((BM / TM) * (BN / TN))
sgemm_kernel(const float* __restrict__ A, const float* __restrict__ B,
             const float* __restrict__ bias, float* __restrict__ C,
             int M, int N, int K, int relu)
{
    constexpr int TX = BN / TN;
    constexpr int TY = BM / TM;
    constexpr int THREADS = TX * TY;
    __shared__ float As[BK][BM];
    __shared__ float Bs[BK][BN];

    const int tid = threadIdx.x;
    const int tx = tid % TX;
    const int ty = tid / TX;
    const int row0 = blockIdx.y * BM;
    const int col0 = blockIdx.x * BN;

    float acc[TM][TN];
#pragma unroll
    for (int i = 0; i < TM; i++)
#pragma unroll
        for (int j = 0; j < TN; j++) acc[i][j] = 0.f;

    for (int k0 = 0; k0 < K; k0 += BK) {
        for (int i = tid; i < BM * BK; i += THREADS) {
            int m = i / BK, k = i % BK;
            int gm = row0 + m, gk = k0 + k;
            As[k][m] = (gm < M && gk < K) ? A[(size_t)gm * K + gk] : 0.f;
        }
        for (int i = tid; i < BK * BN; i += THREADS) {
            int k = i / BN, nn = i % BN;
            int gn = col0 + nn, gk = k0 + k;
            Bs[k][nn] = (gn < N && gk < K) ? B[(size_t)gk * N + gn] : 0.f;
        }
        __syncthreads();
#pragma unroll
        for (int k = 0; k < BK; k++) {
            float ra[TM], rb[TN];
#pragma unroll
            for (int i = 0; i < TM; i++) ra[i] = As[k][ty * TM + i];
#pragma unroll
            for (int j = 0; j < TN; j++) rb[j] = Bs[k][tx * TN + j];
#pragma unroll
            for (int i = 0; i < TM; i++)
#pragma unroll
                for (int j = 0; j < TN; j++) acc[i][j] += ra[i] * rb[j];
        }
        __syncthreads();
    }

#pragma unroll
    for (int i = 0; i < TM; i++) {
        int gm = row0 + ty * TM + i;
        if (gm >= M) continue;
#pragma unroll
        for (int j = 0; j < TN; j++) {
            int gn = col0 + tx * TN + j;
            if (gn >= N) continue;
            float v = acc[i][j];
            if (bias) v += bias[gn];
            if (relu) v = fmaxf(v, 0.f);
            C[(size_t)gm * N + gn] = v;
        }
    }
}

// ---------------- CSR build (edge_index is int32) ---------------------------
__global__ void hist_kernel(const int* __restrict__ ei, int* __restrict__ cnt) {
    int e = blockIdx.x * blockDim.x + threadIdx.x;
    if (e < EE) atomicAdd(&cnt[ei[EE + e]], 1);
}

__global__ void scan_block_kernel(const int* __restrict__ cnt, int* __restrict__ rowptr,
                                  int* __restrict__ bsum, int n) {
    __shared__ int sh[1024];
    const int tid = threadIdx.x;
    const int i = blockIdx.x * 1024 + tid;
    sh[tid] = (i < n) ? cnt[i] : 0;
    __syncthreads();
    for (int off = 1; off < 1024; off <<= 1) {
        int t = (tid >= off) ? sh[tid - off] : 0;
        __syncthreads();
        sh[tid] += t;
        __syncthreads();
    }
    if (i < n) rowptr[i + 1] = sh[tid];
    if (tid == 1023) bsum[blockIdx.x] = sh[1023];
}
__global__ void scan_bsum_kernel(int* __restrict__ bsum, int nb) {
    __shared__ int sh[64];
    const int tid = threadIdx.x;
    sh[tid] = (tid < nb) ? bsum[tid] : 0;
    __syncthreads();
    for (int off = 1; off < 64; off <<= 1) {
        int t = (tid >= off) ? sh[tid - off] : 0;
        __syncthreads();
        sh[tid] += t;
        __syncthreads();
    }
    if (tid < nb) bsum[tid] = (tid == 0) ? 0 : sh[tid - 1];
}
__global__ void scan_add_kernel(int* __restrict__ rowptr, const int* __restrict__ bsum,
                                int n) {
    int i = blockIdx.x * blockDim.x + threadIdx.x;
    if (i == 0) rowptr[0] = 0;
    if (i < n) rowptr[i + 1] += bsum[i >> 10];
}

__global__ void scatter_kernel(const int* __restrict__ ei,
                               const int* __restrict__ rowptr,
                               int* __restrict__ cur, int* __restrict__ colA) {
    int e = blockIdx.x * blockDim.x + threadIdx.x;
    if (e < EE) {
        int d = ei[EE + e];
        int pos = atomicAdd(&cur[d], 1);
        colA[rowptr[d] + pos] = ei[e];
    }
}

// ---------------- GAT aggregation: warp-per-node, no block syncs ------------
#define AGG_WARPS 8
__global__ void __launch_bounds__(AGG_WARPS * 32)
gat_aggregate_kernel(const __half* __restrict__ hp,
                     const float* __restrict__ as_,
                     const float* __restrict__ ad_,
                     const int* __restrict__ rowptr,
                     const int* __restrict__ col,
                     const int* __restrict__ gmax,
                     const float* __restrict__ bias,
                     float* __restrict__ hout) {
    const int warp = threadIdx.x >> 5, lane = threadIdx.x & 31;
    const int n = blockIdx.x * AGG_WARPS + warp;
    if (n >= NN) return;
    const int start = rowptr[n];
    const int deg = rowptr[n + 1] - start;
    const int total = deg + 1;

    const float4 ad4 = *(const float4*)(ad_ + n * HH);
    float4 mh;
    mh.x = leaky02(ord2f(gmax[0]) + ad4.x);
    mh.y = leaky02(ord2f(gmax[1]) + ad4.y);
    mh.z = leaky02(ord2f(gmax[2]) + ad4.z);
    mh.w = leaky02(ord2f(gmax[3]) + ad4.w);

    __shared__ float4 wsm[AGG_WARPS][32];
    __shared__ int    ssm[AGG_WARPS][32];

    const int hoff = lane * 8;
    float acc0[8], acc1[8];
#pragma unroll
    for (int k = 0; k < 8; k++) { acc0[k] = 0.f; acc1[k] = 0.f; }
    float4 dl = make_float4(0.f, 0.f, 0.f, 0.f);

    for (int base = 0; base < total; base += 32) {
        const int cnt = min(32, total - base);
        if (lane < cnt) {
            const int i = base + lane;
            const int s = (i < deg) ? col[start + i] : n;
            const float4 a4 = *(const float4*)(as_ + s * HH);
            float4 w4;
            w4.x = __expf(leaky02(a4.x + ad4.x) - mh.x);
            w4.y = __expf(leaky02(a4.y + ad4.y) - mh.y);
            w4.z = __expf(leaky02(a4.z + ad4.z) - mh.z);
            w4.w = __expf(leaky02(a4.w + ad4.w) - mh.w);
            dl.x += w4.x; dl.y += w4.y; dl.z += w4.z; dl.w += w4.w;
            wsm[warp][lane] = w4;
            ssm[warp][lane] = s;
        }
        __syncwarp();
#pragma unroll 2
        for (int j = 0; j < cnt; j++) {
            const int sj = ssm[warp][j];
            const float4 w4 = wsm[warp][j];
            const float wa = (lane & 16) ? w4.y : w4.x;
            const float wb = (lane & 16) ? w4.w : w4.z;
            const uint4 u0 = *(const uint4*)(hp + (size_t)sj * (HH * DD) + hoff);
            const uint4 u1 = *(const uint4*)(hp + (size_t)sj * (HH * DD) + 256 + hoff);
            const __half2* p0 = (const __half2*)&u0;
            const __half2* p1 = (const __half2*)&u1;
#pragma unroll
            for (int k = 0; k < 4; k++) {
                const float2 f0 = __half22float2(p0[k]);
                const float2 f1 = __half22float2(p1[k]);
                acc0[2 * k]     += wa * f0.x;
                acc0[2 * k + 1] += wa * f0.y;
                acc1[2 * k]     += wb * f1.x;
                acc1[2 * k + 1] += wb * f1.y;
            }
        }
        __syncwarp();
    }

#pragma unroll
    for (int off = 16; off; off >>= 1) {
        dl.x += __shfl_xor_sync(0xffffffffu, dl.x, off);
        dl.y += __shfl_xor_sync(0xffffffffu, dl.y, off);
        dl.z += __shfl_xor_sync(0xffffffffu, dl.z, off);
        dl.w += __shfl_xor_sync(0xffffffffu, dl.w, off);
    }
    const float da = 1.f / (((lane & 16) ? dl.y : dl.x) + 1e-16f);
    const float db = 1.f / (((lane & 16) ? dl.w : dl.z) + 1e-16f);

    float outv[8];
#pragma unroll
    for (int k = 0; k < 8; k++) {
        float part = acc0[k] * da + acc1[k] * db;
        part += __shfl_xor_sync(0xffffffffu, part, 16);
        outv[k] = 0.25f * part;
    }
    if (lane < 16) {
        const int c = lane * 8;
        float4 b0 = *(const float4*)(bias + c);
        float4 b1 = *(const float4*)(bias + c + 4);
        float4 o0 = make_float4(outv[0] + b0.x, outv[1] + b0.y,
                                outv[2] + b0.z, outv[3] + b0.w);
        float4 o1 = make_float4(outv[4] + b1.x, outv[5] + b1.y,
                                outv[6] + b1.z, outv[7] + b1.w);
        *(float4*)(hout + (size_t)n * DD + c) = o0;
        *(float4*)(hout + (size_t)n * DD + c + 4) = o1;
    }
}

// ---------------- pooling (sorted batch -> contiguous ranges) ---------------
__global__ void batch_hist_kernel(const int* __restrict__ batch, int* __restrict__ gcnt) {
    int i = blockIdx.x * blockDim.x + threadIdx.x;
    if (i < NN) atomicAdd(&gcnt[batch[i]], 1);
}
__global__ void gscan_kernel(const int* __restrict__ gcnt, int* __restrict__ goff) {
    __shared__ int sh[GG];
    const int tid = threadIdx.x;
    sh[tid] = gcnt[tid];
    __syncthreads();
    for (int off = 1; off < GG; off <<= 1) {
        int t = (tid >= off) ? sh[tid - off] : 0;
        __syncthreads();
        sh[tid] += t;
        __syncthreads();
    }
    if (tid == 0) goff[0] = 0;
    goff[tid + 1] = sh[tid];
}
__global__ void pool_kernel(const float* __restrict__ hin,
                            const int* __restrict__ goff,
                            float* __restrict__ pooled) {
    int g = blockIdx.x;
    int c = threadIdx.x;
    int s = goff[g], e = goff[g + 1];
    float acc = 0.f;
    for (int i = s; i < e; i++) acc += hin[(size_t)i * DD + c];
    pooled[g * DD + c] = acc / fmaxf((float)(e - s), 1.f);
}

// ---------------- launch ----------------------------------------------------
extern "C" void kernel_launch(void* const* d_in, const int* in_sizes, int n_in,
                              void* d_out, int out_size) {
    const float* x       = (const float*)d_in[0];
    const int*   ei      = (const int*)d_in[1];
    const int*   batch   = (const int*)d_in[2];
    const float* W1      = (const float*)d_in[3];
    const float* b1      = (const float*)d_in[4];
    const float* W2      = (const float*)d_in[5];
    const float* b2      = (const float*)d_in[6];
    const float* lin_w   = (const float*)d_in[7];
    const float* att_src = (const float*)d_in[8];
    const float* att_dst = (const float*)d_in[9];
    const float* conv_b  = (const float*)d_in[10];
    const float* gW1     = (const float*)d_in[11];
    const float* gb1     = (const float*)d_in[12];
    const float* gW2     = (const float*)d_in[13];
    const float* gb2     = (const float*)d_in[14];
    float*       out     = (float*)d_out;

    float *h, *hn, *as_, *ad_, *pooled, *hidden, *wT;
    __half* hp;
    int *rowptr, *cnt, *cur, *colA, *gcnt, *goff, *bsum, *gmax;
    cudaGetSymbolAddress((void**)&h, g_h);
    cudaGetSymbolAddress((void**)&hp, g_hp);
    cudaGetSymbolAddress((void**)&hn, g_hn);
    cudaGetSymbolAddress((void**)&as_, g_as);
    cudaGetSymbolAddress((void**)&ad_, g_ad);
    cudaGetSymbolAddress((void**)&rowptr, g_rowptr);
    cudaGetSymbolAddress((void**)&cnt, g_cnt);
    cudaGetSymbolAddress((void**)&cur, g_cur);
    cudaGetSymbolAddress((void**)&colA, g_col);
    cudaGetSymbolAddress((void**)&bsum, g_bsum);
    cudaGetSymbolAddress((void**)&gmax, g_gmax);
    cudaGetSymbolAddress((void**)&pooled, g_pooled);
    cudaGetSymbolAddress((void**)&gcnt, g_gcnt);
    cudaGetSymbolAddress((void**)&goff, g_goff);
    cudaGetSymbolAddress((void**)&hidden, g_hidden);
    cudaGetSymbolAddress((void**)&wT, g_wT);

    float* w1T  = wT;                                    // [128][128]
    float* w2T  = wT + 128 * 128;                        // [128][128]
    float* linT = wT + 2 * 128 * 128;                    // [3][512][128]
    float* gW1T = wT + 2 * 128 * 128 + 3 * 512 * 128;    // [1024][128]
    float* xpad = (float*)hp;                            // 25.6 MB scratch inside g_hp

    cudaFuncSetAttribute(h16_gemm_fused,
                         cudaFuncAttributeMaxDynamicSharedMemorySize, SM_BYTES);

    auto cdiv = [](int a, int b) { return (a + b - 1) / b; };
    const int MT = cdiv(NN, BMROWS);  // 391 m-tiles of 128 rows
    const int NB = cdiv(NN, 1024);    // 49 scan blocks

    // 0) init counters/sentinels + batched weight transpose + pad x
    init_misc_kernel<<<cdiv(NN, 256), 256>>>(cnt, cur, gcnt, gmax);
    transpose_all_kernel<<<dim3(32, 4, 6), dim3(32, 8)>>>(
        W1, W2, lin_w, gW1, w1T, w2T, linT, gW1T);
    pad_x_kernel<<<cdiv(NN * 32, 256), 256>>>(x, xpad);

    // 1) node MLP via tensor cores (xpad -> hn -> h)
    h16_gemm_fused<<<dim3(1, MT), GTHREADS, SM_BYTES>>>(
        xpad, NN, w1T, b1, hn, DD, 1, 0, nullptr, nullptr, nullptr, nullptr, nullptr);
    h16_gemm_fused<<<dim3(1, MT), GTHREADS, SM_BYTES>>>(
        hn, NN, w2T, b2, h, DD, 0, 0, nullptr, nullptr, nullptr, nullptr, nullptr);

    // 2) CSR by destination + batch offsets
    hist_kernel<<<cdiv(EE, 256), 256>>>(ei, cnt);
    scan_block_kernel<<<NB, 1024>>>(cnt, rowptr, bsum, NN);
    scan_bsum_kernel<<<1, 64>>>(bsum, NB);
    scan_add_kernel<<<cdiv(NN, 256), 256>>>(rowptr, bsum, NN);
    scatter_kernel<<<cdiv(EE, 256), 256>>>(ei, rowptr, cur, colA);
    batch_hist_kernel<<<cdiv(NN, 256), 256>>>(batch, gcnt);
    gscan_kernel<<<1, 1024>>>(gcnt, goff);

    // 3) GAT layers (gmax bound fused into GEMM epilogue)
    float* hin = h;
    float* hout = hn;
    for (int l = 0; l < LL; l++) {
        h16_gemm_fused<<<dim3(HH, MT), GTHREADS, SM_BYTES>>>(
            hin, NN, linT + (size_t)l * 512 * 128, nullptr, hp, HH * DD, 0, 1,
            att_src + l * HH * DD, att_dst + l * HH * DD, as_, ad_, gmax + l * HH);
        gat_aggregate_kernel<<<cdiv(NN, AGG_WARPS), AGG_WARPS * 32>>>(
            hp, as_, ad_, rowptr, colA, gmax + l * HH, conv_b + l * DD, hout);
        float* t = hin; hin = hout; hout = t;
    }

    // 4) global mean pool (atomic-free; batch is sorted)
    pool_kernel<<<GG, DD>>>(hin, goff, pooled);

    // 5) FC head: FC1 on tensor cores, FC2 (K=1024) SIMT
    h16_gemm_fused<<<dim3(8, cdiv(GG, BMROWS)), GTHREADS, SM_BYTES>>>(
        pooled, GG, gW1T, gb1, hidden, HID, 1, 0, nullptr, nullptr, nullptr, nullptr,
        nullptr);
    sgemm_kernel<64, 64, 8, 4, 4><<<dim3(cdiv(DD, 64), cdiv(GG, 64)), 256>>>(
        hidden, gW2, gb2, out, GG, DD, HID, 0);
}

// round 16
// speedup vs baseline: 1.1175x; 1.1175x over previous
#include <cuda_runtime.h>
#include <cuda_fp16.h>
#include <cstdint>

#define NN 50000
#define EE 800000
#define GG 1024
#define DD 128
#define HH 4
#define LL 3
#define NODE_DIM 78
#define HID 1024

// ---------------- scratch (device globals; no allocation allowed) ----------
__device__ __half g_h[NN * DD];
__device__ __half g_hp[(size_t)NN * HH * DD];   // 51.2 MB; front also x-pad scratch
__device__ __half g_hn[NN * DD];
__device__ float g_as[NN * HH];
__device__ float g_ad[NN * HH];
__device__ int   g_rowptr[NN + 1];
__device__ int   g_cnt[NN];
__device__ int   g_cur[NN];
__device__ int   g_col[EE];
__device__ int   g_bsum[64];
__device__ int   g_gmax[LL * HH];
__device__ __half g_pooled[GG * DD];
__device__ int   g_gcnt[GG];
__device__ int   g_goff[GG + 1];
__device__ float g_hidden[GG * HID];
// transposed / K-padded fp16 weights: W1T, W2T, lin_wT[3][512][128], gW1T[1024][128]
__device__ __half g_wT[2 * 128 * 128 + 3 * 512 * 128 + 1024 * 128];

__device__ __forceinline__ int f2ord(float f) {
    int i = __float_as_int(f);
    return (i >= 0) ? i : i ^ 0x7FFFFFFF;
}
__device__ __forceinline__ float ord2f(int i) {
    return __int_as_float((i >= 0) ? i : i ^ 0x7FFFFFFF);
}
__device__ __forceinline__ float leaky02(float e) { return e > 0.f ? e : 0.2f * e; }

// ---------------- init: zero cnt/cur/gcnt, set gmax sentinels ---------------
__global__ void init_misc_kernel(int* cnt, int* cur, int* gcnt, int* gmax) {
    int i = blockIdx.x * blockDim.x + threadIdx.x;
    if (i < NN) { cnt[i] = 0; cur[i] = 0; }
    if (i < GG) gcnt[i] = 0;
    if (i < LL * HH) gmax[i] = f2ord(-3.0e38f);
}

// ---------------- pad x [NN,78] fp32 -> xp [NN,128] fp16 --------------------
__global__ void pad_x_kernel(const float* __restrict__ x, __half* __restrict__ xp) {
    int idx = blockIdx.x * blockDim.x + threadIdx.x;
    if (idx >= NN * 32) return;
    int row = idx >> 5;
    int q = idx & 31;
    int c = q * 4;
    const float* xr = x + (size_t)row * NODE_DIM;
    float4 v = make_float4(0.f, 0.f, 0.f, 0.f);
    if (c + 3 < NODE_DIM) {
        v.x = xr[c]; v.y = xr[c + 1]; v.z = xr[c + 2]; v.w = xr[c + 3];
    } else {
        if (c < NODE_DIM) v.x = xr[c];
        if (c + 1 < NODE_DIM) v.y = xr[c + 1];
        if (c + 2 < NODE_DIM) v.z = xr[c + 2];
        if (c + 3 < NODE_DIM) v.w = xr[c + 3];
    }
    __half2 p0 = __floats2half2_rn(v.x, v.y);
    __half2 p1 = __floats2half2_rn(v.z, v.w);
    uint2 u;
    u.x = *(uint32_t*)&p0;
    u.y = *(uint32_t*)&p1;
    *(uint2*)(xp + (size_t)row * 128 + c) = u;
}

// ---------------- batched transpose + pad-K of all 6 weights (fp16 out) -----
__global__ void transpose_all_kernel(const float* __restrict__ W1,
                                     const float* __restrict__ W2,
                                     const float* __restrict__ lin_w,
                                     const float* __restrict__ gW1,
                                     __half* __restrict__ w1T,
                                     __half* __restrict__ w2T,
                                     __half* __restrict__ linT,
                                     __half* __restrict__ gW1T) {
    __shared__ float t[32][33];
    const int job = blockIdx.z;
    const float* src; __half* dst; int K, Nsrc;
    switch (job) {
        case 0: src = W1; dst = w1T; K = NODE_DIM; Nsrc = 128; break;
        case 1: src = W2; dst = w2T; K = 128; Nsrc = 128; break;
        case 5: src = gW1; dst = gW1T; K = 128; Nsrc = 1024; break;
        default:
            src = lin_w + (size_t)(job - 2) * 128 * 512;
            dst = linT + (size_t)(job - 2) * 512 * 128;
            K = 128; Nsrc = 512; break;
    }
    int n0 = blockIdx.x * 32, k0 = blockIdx.y * 32;
    if (n0 >= Nsrc) return;
    int tx = threadIdx.x, ty = threadIdx.y;
#pragma unroll
    for (int i = 0; i < 32; i += 8) {
        int k = k0 + ty + i, n = n0 + tx;
        t[ty + i][tx] = (k < K && n < Nsrc) ? src[(size_t)k * Nsrc + n] : 0.f;
    }
    __syncthreads();
#pragma unroll
    for (int i = 0; i < 32; i += 8) {
        int n = n0 + ty + i, k = k0 + tx;
        if (n < Nsrc) dst[(size_t)n * 128 + k] = __float2half(t[tx][ty + i]);
    }
}

// ---------------- fp16 mma.sync GEMM, tile 256x128, K=128, fused epilogue --
// 512 threads = 16 warps in 8x2 grid. A/B already fp16 -> pure uint4 loads.
#define HS 136
#define BMROWS 256
#define GTHREADS 512
#define A_BYTES (BMROWS * HS * 2)
#define B_BYTES (128 * HS * 2)
#define ASBUF_OFF (A_BYTES + B_BYTES)
#define SM_BYTES (ASBUF_OFF + 2 * BMROWS * 4)

__global__ void __launch_bounds__(GTHREADS)
h16_gemm_fused(const __half* __restrict__ A, int M,
               const __half* __restrict__ Bt,    // [nChunks*128][128] fp16
               const float* __restrict__ bias,   // global-col indexed or null
               void* __restrict__ C, int c_stride,
               int relu, int half_out,
               const float* __restrict__ attS,   // global-col indexed or null
               const float* __restrict__ attD,
               float* __restrict__ asOut, float* __restrict__ adOut,
               int* __restrict__ gmaxOut)
{
    extern __shared__ char smc[];
    __half* As = (__half*)smc;
    __half* Bs = (__half*)(smc + A_BYTES);
    float* asbuf = (float*)(smc + ASBUF_OFF);
    float* adbuf = asbuf + BMROWS;

    const int tid = threadIdx.x;
    const int wid = tid >> 5, lane = tid & 31;
    const int grp = lane >> 2, tig = lane & 3;
    const int wm = wid & 7, wn = wid >> 3;      // 8 x 2 warp grid
    const int nc = blockIdx.x;
    const int m0 = blockIdx.y * BMROWS;
    const int rows = min(BMROWS, M - m0);
    const int colg0 = nc * 128;

    // ---- load tiles to SMEM: pure 16B copies (8 halves each) ----
    {
        const uint4* src = (const uint4*)(A + (size_t)m0 * 128);
        for (int idx = tid; idx < BMROWS * 16; idx += GTHREADS) {
            int row = idx >> 4, q = idx & 15;
            uint4 u = make_uint4(0u, 0u, 0u, 0u);
            if (row < rows) u = src[row * 16 + q];
            *(uint4*)(As + row * HS + q * 8) = u;
        }
    }
    {
        const uint4* src = (const uint4*)(Bt + (size_t)nc * 128 * 128);
        for (int idx = tid; idx < 128 * 16; idx += GTHREADS) {
            int row = idx >> 4, q = idx & 15;
            uint4 u = src[row * 16 + q];
            *(uint4*)(Bs + row * HS + q * 8) = u;
        }
    }
    if (tid < BMROWS) { asbuf[tid] = 0.f; adbuf[tid] = 0.f; }
    __syncthreads();

    // ---- main MMA loop: 8 k-steps of m16n8k16 ----
    float acc[2][8][4];
#pragma unroll
    for (int mi = 0; mi < 2; mi++)
#pragma unroll
        for (int ni = 0; ni < 8; ni++)
#pragma unroll
            for (int q = 0; q < 4; q++) acc[mi][ni][q] = 0.f;

#pragma unroll
    for (int ks = 0; ks < 8; ks++) {
        const int k0 = ks * 16;
        uint32_t a[2][4];
#pragma unroll
        for (int mi = 0; mi < 2; mi++) {
            int rb = wm * 32 + mi * 16 + grp;
            a[mi][0] = *(const uint32_t*)(As + rb * HS + k0 + 2 * tig);
            a[mi][1] = *(const uint32_t*)(As + (rb + 8) * HS + k0 + 2 * tig);
            a[mi][2] = *(const uint32_t*)(As + rb * HS + k0 + 2 * tig + 8);
            a[mi][3] = *(const uint32_t*)(As + (rb + 8) * HS + k0 + 2 * tig + 8);
        }
        uint32_t b[8][2];
#pragma unroll
        for (int ni = 0; ni < 8; ni++) {
            int cb = wn * 64 + ni * 8 + grp;
            b[ni][0] = *(const uint32_t*)(Bs + cb * HS + k0 + 2 * tig);
            b[ni][1] = *(const uint32_t*)(Bs + cb * HS + k0 + 2 * tig + 8);
        }
#pragma unroll
        for (int mi = 0; mi < 2; mi++)
#pragma unroll
            for (int ni = 0; ni < 8; ni++) {
                asm volatile(
                    "mma.sync.aligned.m16n8k16.row.col.f32.f16.f16.f32 "
                    "{%0,%1,%2,%3}, {%4,%5,%6,%7}, {%8,%9}, {%0,%1,%2,%3};"
                    : "+f"(acc[mi][ni][0]), "+f"(acc[mi][ni][1]),
                      "+f"(acc[mi][ni][2]), "+f"(acc[mi][ni][3])
                    : "r"(a[mi][0]), "r"(a[mi][1]), "r"(a[mi][2]), "r"(a[mi][3]),
                      "r"(b[ni][0]), "r"(b[ni][1]));
            }
    }

    // ---- epilogue: bias/relu/store + fused attention dots ----
#pragma unroll
    for (int mi = 0; mi < 2; mi++) {
        const int r0 = wm * 32 + mi * 16 + grp;
        const int r1 = r0 + 8;
        const int gm0 = m0 + r0, gm1 = m0 + r1;
        float aS0 = 0.f, aD0 = 0.f, aS1 = 0.f, aD1 = 0.f;
#pragma unroll
        for (int ni = 0; ni < 8; ni++) {
            const int col = wn * 64 + ni * 8 + tig * 2;
            const int cg = colg0 + col;
            float v0 = acc[mi][ni][0], v1 = acc[mi][ni][1];
            float v2 = acc[mi][ni][2], v3 = acc[mi][ni][3];
            if (bias) {
                float b0 = bias[cg], b1 = bias[cg + 1];
                v0 += b0; v1 += b1; v2 += b0; v3 += b1;
            }
            if (relu) {
                v0 = fmaxf(v0, 0.f); v1 = fmaxf(v1, 0.f);
                v2 = fmaxf(v2, 0.f); v3 = fmaxf(v3, 0.f);
            }
            if (attS) {
                float s0 = attS[cg], s1 = attS[cg + 1];
                float d0 = attD[cg], d1 = attD[cg + 1];
                aS0 += v0 * s0 + v1 * s1;
                aD0 += v0 * d0 + v1 * d1;
                aS1 += v2 * s0 + v3 * s1;
                aD1 += v2 * d0 + v3 * d1;
            }
            if (half_out) {
                __half* Ch = (__half*)C;
                if (gm0 < M)
                    *(__half2*)(Ch + (size_t)gm0 * c_stride + cg) = __floats2half2_rn(v0, v1);
                if (gm1 < M)
                    *(__half2*)(Ch + (size_t)gm1 * c_stride + cg) = __floats2half2_rn(v2, v3);
            } else {
                float* Cf = (float*)C;
                if (gm0 < M) *(float2*)(Cf + (size_t)gm0 * c_stride + cg) = make_float2(v0, v1);
                if (gm1 < M) *(float2*)(Cf + (size_t)gm1 * c_stride + cg) = make_float2(v2, v3);
            }
        }
        if (attS) {
#pragma unroll
            for (int off = 1; off < 4; off <<= 1) {
                aS0 += __shfl_xor_sync(0xffffffffu, aS0, off);
                aD0 += __shfl_xor_sync(0xffffffffu, aD0, off);
                aS1 += __shfl_xor_sync(0xffffffffu, aS1, off);
                aD1 += __shfl_xor_sync(0xffffffffu, aD1, off);
            }
            if (tig == 0) {
                atomicAdd(&asbuf[r0], aS0);
                atomicAdd(&adbuf[r0], aD0);
                atomicAdd(&asbuf[r1], aS1);
                atomicAdd(&adbuf[r1], aD1);
            }
        }
    }
    if (attS) {
        __syncthreads();
        if (tid < BMROWS && m0 + tid < M) {
            asOut[(m0 + tid) * HH + nc] = asbuf[tid];
            adOut[(m0 + tid) * HH + nc] = adbuf[tid];
        }
        // fused per-head global max bound (warp 15)
        if (wid == 15) {
            float m = -3.0e38f;
            for (int i = lane; i < rows; i += 32) m = fmaxf(m, asbuf[i]);
#pragma unroll
            for (int off = 16; off; off >>= 1)
                m = fmaxf(m, __shfl_xor_sync(0xffffffffu, m, off));
            if (lane == 0) atomicMax(gmaxOut + nc, f2ord(m));
        }
    }
}

// ---------------- SIMT SGEMM (FC2 only: K=1024) ------------------------------
template <int BM, int BN, int BK, int TM, int TN>
__global__ void __launch_bounds__((BM / TM) * (BN / TN))
sgemm_kernel(const float* __restrict__ A, const float* __restrict__ B,
             const float* __restrict__ bias, float* __restrict__ C,
             int M, int N, int K, int relu)
{
    constexpr int TX = BN / TN;
    constexpr int TY = BM / TM;
    constexpr int THREADS = TX * TY;
    __shared__ float As[BK][BM];
    __shared__ float Bs[BK][BN];

    const int tid = threadIdx.x;
    const int tx = tid % TX;
    const int ty = tid / TX;
    const int row0 = blockIdx.y * BM;
    const int col0 = blockIdx.x * BN;

    float acc[TM][TN];
#pragma unroll
    for (int i = 0; i < TM; i++)
#pragma unroll
        for (int j = 0; j < TN; j++) acc[i][j] = 0.f;

    for (int k0 = 0; k0 < K; k0 += BK) {
        for (int i = tid; i < BM * BK; i += THREADS) {
            int m = i / BK, k = i % BK;
            int gm = row0 + m, gk = k0 + k;
            As[k][m] = (gm < M && gk < K) ? A[(size_t)gm * K + gk] : 0.f;
        }
        for (int i = tid; i < BK * BN; i += THREADS) {
            int k = i / BN, nn = i % BN;
            int gn = col0 + nn, gk = k0 + k;
            Bs[k][nn] = (gn < N && gk < K) ? B[(size_t)gk * N + gn] : 0.f;
        }
        __syncthreads();
#pragma unroll
        for (int k = 0; k < BK; k++) {
            float ra[TM], rb[TN];
#pragma unroll
            for (int i = 0; i < TM; i++) ra[i] = As[k][ty * TM + i];
#pragma unroll
            for (int j = 0; j < TN; j++) rb[j] = Bs[k][tx * TN + j];
#pragma unroll
            for (int i = 0; i < TM; i++)
#pragma unroll
                for (int j = 0; j < TN; j++) acc[i][j] += ra[i] * rb[j];
        }
        __syncthreads();
    }

#pragma unroll
    for (int i = 0; i < TM; i++) {
        int gm = row0 + ty * TM + i;
        if (gm >= M) continue;
#pragma unroll
        for (int j = 0; j < TN; j++) {
            int gn = col0 + tx * TN + j;
            if (gn >= N) continue;
            float v = acc[i][j];
            if (bias) v += bias[gn];
            if (relu) v = fmaxf(v, 0.f);
            C[(size_t)gm * N + gn] = v;
        }
    }
}

// ---------------- CSR build (edge_index is int32) ---------------------------
__global__ void hist_kernel(const int* __restrict__ ei, int* __restrict__ cnt) {
    int e = blockIdx.x * blockDim.x + threadIdx.x;
    if (e < EE) atomicAdd(&cnt[ei[EE + e]], 1);
}

__global__ void scan_block_kernel(const int* __restrict__ cnt, int* __restrict__ rowptr,
                                  int* __restrict__ bsum, int n) {
    __shared__ int sh[1024];
    const int tid = threadIdx.x;
    const int i = blockIdx.x * 1024 + tid;
    sh[tid] = (i < n) ? cnt[i] : 0;
    __syncthreads();
    for (int off = 1; off < 1024; off <<= 1) {
        int t = (tid >= off) ? sh[tid - off] : 0;
        __syncthreads();
        sh[tid] += t;
        __syncthreads();
    }
    if (i < n) rowptr[i + 1] = sh[tid];
    if (tid == 1023) bsum[blockIdx.x] = sh[1023];
}
__global__ void scan_bsum_kernel(int* __restrict__ bsum, int nb) {
    __shared__ int sh[64];
    const int tid = threadIdx.x;
    sh[tid] = (tid < nb) ? bsum[tid] : 0;
    __syncthreads();
    for (int off = 1; off < 64; off <<= 1) {
        int t = (tid >= off) ? sh[tid - off] : 0;
        __syncthreads();
        sh[tid] += t;
        __syncthreads();
    }
    if (tid < nb) bsum[tid] = (tid == 0) ? 0 : sh[tid - 1];
}
__global__ void scan_add_kernel(int* __restrict__ rowptr, const int* __restrict__ bsum,
                                int n) {
    int i = blockIdx.x * blockDim.x + threadIdx.x;
    if (i == 0) rowptr[0] = 0;
    if (i < n) rowptr[i + 1] += bsum[i >> 10];
}

__global__ void scatter_kernel(const int* __restrict__ ei,
                               const int* __restrict__ rowptr,
                               int* __restrict__ cur, int* __restrict__ colA) {
    int e = blockIdx.x * blockDim.x + threadIdx.x;
    if (e < EE) {
        int d = ei[EE + e];
        int pos = atomicAdd(&cur[d], 1);
        colA[rowptr[d] + pos] = ei[e];
    }
}

// ---------------- GAT aggregation: warp-per-node, no block syncs ------------
#define AGG_WARPS 8
__global__ void __launch_bounds__(AGG_WARPS * 32)
gat_aggregate_kernel(const __half* __restrict__ hp,
                     const float* __restrict__ as_,
                     const float* __restrict__ ad_,
                     const int* __restrict__ rowptr,
                     const int* __restrict__ col,
                     const int* __restrict__ gmax,
                     const float* __restrict__ bias,
                     __half* __restrict__ hout) {
    const int warp = threadIdx.x >> 5, lane = threadIdx.x & 31;
    const int n = blockIdx.x * AGG_WARPS + warp;
    if (n >= NN) return;
    const int start = rowptr[n];
    const int deg = rowptr[n + 1] - start;
    const int total = deg + 1;

    const float4 ad4 = *(const float4*)(ad_ + n * HH);
    float4 mh;
    mh.x = leaky02(ord2f(gmax[0]) + ad4.x);
    mh.y = leaky02(ord2f(gmax[1]) + ad4.y);
    mh.z = leaky02(ord2f(gmax[2]) + ad4.z);
    mh.w = leaky02(ord2f(gmax[3]) + ad4.w);

    __shared__ float4 wsm[AGG_WARPS][32];
    __shared__ int    ssm[AGG_WARPS][32];

    const int hoff = lane * 8;
    float acc0[8], acc1[8];
#pragma unroll
    for (int k = 0; k < 8; k++) { acc0[k] = 0.f; acc1[k] = 0.f; }
    float4 dl = make_float4(0.f, 0.f, 0.f, 0.f);

    for (int base = 0; base < total; base += 32) {
        const int cnt = min(32, total - base);
        if (lane < cnt) {
            const int i = base + lane;
            const int s = (i < deg) ? col[start + i] : n;
            const float4 a4 = *(const float4*)(as_ + s * HH);
            float4 w4;
            w4.x = __expf(leaky02(a4.x + ad4.x) - mh.x);
            w4.y = __expf(leaky02(a4.y + ad4.y) - mh.y);
            w4.z = __expf(leaky02(a4.z + ad4.z) - mh.z);
            w4.w = __expf(leaky02(a4.w + ad4.w) - mh.w);
            dl.x += w4.x; dl.y += w4.y; dl.z += w4.z; dl.w += w4.w;
            wsm[warp][lane] = w4;
            ssm[warp][lane] = s;
        }
        __syncwarp();
#pragma unroll 2
        for (int j = 0; j < cnt; j++) {
            const int sj = ssm[warp][j];
            const float4 w4 = wsm[warp][j];
            const float wa = (lane & 16) ? w4.y : w4.x;
            const float wb = (lane & 16) ? w4.w : w4.z;
            const uint4 u0 = *(const uint4*)(hp + (size_t)sj * (HH * DD) + hoff);
            const uint4 u1 = *(const uint4*)(hp + (size_t)sj * (HH * DD) + 256 + hoff);
            const __half2* p0 = (const __half2*)&u0;
            const __half2* p1 = (const __half2*)&u1;
#pragma unroll
            for (int k = 0; k < 4; k++) {
                const float2 f0 = __half22float2(p0[k]);
                const float2 f1 = __half22float2(p1[k]);
                acc0[2 * k]     += wa * f0.x;
                acc0[2 * k + 1] += wa * f0.y;
                acc1[2 * k]     += wb * f1.x;
                acc1[2 * k + 1] += wb * f1.y;
            }
        }
        __syncwarp();
    }

#pragma unroll
    for (int off = 16; off; off >>= 1) {
        dl.x += __shfl_xor_sync(0xffffffffu, dl.x, off);
        dl.y += __shfl_xor_sync(0xffffffffu, dl.y, off);
        dl.z += __shfl_xor_sync(0xffffffffu, dl.z, off);
        dl.w += __shfl_xor_sync(0xffffffffu, dl.w, off);
    }
    const float da = 1.f / (((lane & 16) ? dl.y : dl.x) + 1e-16f);
    const float db = 1.f / (((lane & 16) ? dl.w : dl.z) + 1e-16f);

    float outv[8];
#pragma unroll
    for (int k = 0; k < 8; k++) {
        float part = acc0[k] * da + acc1[k] * db;
        part += __shfl_xor_sync(0xffffffffu, part, 16);
        outv[k] = 0.25f * part;
    }
    if (lane < 16) {
        const int c = lane * 8;
        float4 b0 = *(const float4*)(bias + c);
        float4 b1 = *(const float4*)(bias + c + 4);
        __half2 h0 = __floats2half2_rn(outv[0] + b0.x, outv[1] + b0.y);
        __half2 h1 = __floats2half2_rn(outv[2] + b0.z, outv[3] + b0.w);
        __half2 h2 = __floats2half2_rn(outv[4] + b1.x, outv[5] + b1.y);
        __half2 h3 = __floats2half2_rn(outv[6] + b1.z, outv[7] + b1.w);
        uint4 u;
        u.x = *(uint32_t*)&h0; u.y = *(uint32_t*)&h1;
        u.z = *(uint32_t*)&h2; u.w = *(uint32_t*)&h3;
        *(uint4*)(hout + (size_t)n * DD + c) = u;
    }
}

// ---------------- pooling (sorted batch -> contiguous ranges) ---------------
__global__ void batch_hist_kernel(const int* __restrict__ batch, int* __restrict__ gcnt) {
    int i = blockIdx.x * blockDim.x + threadIdx.x;
    if (i < NN) atomicAdd(&gcnt[batch[i]], 1);
}
__global__ void gscan_kernel(const int* __restrict__ gcnt, int* __restrict__ goff) {
    __shared__ int sh[GG];
    const int tid = threadIdx.x;
    sh[tid] = gcnt[tid];
    __syncthreads();
    for (int off = 1; off < GG; off <<= 1) {
        int t = (tid >= off) ? sh[tid - off] : 0;
        __syncthreads();
        sh[tid] += t;
        __syncthreads();
    }
    if (tid == 0) goff[0] = 0;
    goff[tid + 1] = sh[tid];
}
__global__ void pool_kernel(const __half* __restrict__ hin,
                            const int* __restrict__ goff,
                            __half* __restrict__ pooled) {
    int g = blockIdx.x;
    int c = threadIdx.x;
    int s = goff[g], e = goff[g + 1];
    float acc = 0.f;
    for (int i = s; i < e; i++) acc += __half2float(hin[(size_t)i * DD + c]);
    pooled[g * DD + c] = __float2half(acc / fmaxf((float)(e - s), 1.f));
}

// ---------------- launch ----------------------------------------------------
extern "C" void kernel_launch(void* const* d_in, const int* in_sizes, int n_in,
                              void* d_out, int out_size) {
    const float* x       = (const float*)d_in[0];
    const int*   ei      = (const int*)d_in[1];
    const int*   batch   = (const int*)d_in[2];
    const float* W1      = (const float*)d_in[3];
    const float* b1      = (const float*)d_in[4];
    const float* W2      = (const float*)d_in[5];
    const float* b2      = (const float*)d_in[6];
    const float* lin_w   = (const float*)d_in[7];
    const float* att_src = (const float*)d_in[8];
    const float* att_dst = (const float*)d_in[9];
    const float* conv_b  = (const float*)d_in[10];
    const float* gW1     = (const float*)d_in[11];
    const float* gb1     = (const float*)d_in[12];
    const float* gW2     = (const float*)d_in[13];
    const float* gb2     = (const float*)d_in[14];
    float*       out     = (float*)d_out;

    float *as_, *ad_, *hidden;
    __half *h, *hn, *hp, *pooled, *wT;
    int *rowptr, *cnt, *cur, *colA, *gcnt, *goff, *bsum, *gmax;
    cudaGetSymbolAddress((void**)&h, g_h);
    cudaGetSymbolAddress((void**)&hp, g_hp);
    cudaGetSymbolAddress((void**)&hn, g_hn);
    cudaGetSymbolAddress((void**)&as_, g_as);
    cudaGetSymbolAddress((void**)&ad_, g_ad);
    cudaGetSymbolAddress((void**)&rowptr, g_rowptr);
    cudaGetSymbolAddress((void**)&cnt, g_cnt);
    cudaGetSymbolAddress((void**)&cur, g_cur);
    cudaGetSymbolAddress((void**)&colA, g_col);
    cudaGetSymbolAddress((void**)&bsum, g_bsum);
    cudaGetSymbolAddress((void**)&gmax, g_gmax);
    cudaGetSymbolAddress((void**)&pooled, g_pooled);
    cudaGetSymbolAddress((void**)&gcnt, g_gcnt);
    cudaGetSymbolAddress((void**)&goff, g_goff);
    cudaGetSymbolAddress((void**)&hidden, g_hidden);
    cudaGetSymbolAddress((void**)&wT, g_wT);

    __half* w1T  = wT;                                    // [128][128]
    __half* w2T  = wT + 128 * 128;                        // [128][128]
    __half* linT = wT + 2 * 128 * 128;                    // [3][512][128]
    __half* gW1T = wT + 2 * 128 * 128 + 3 * 512 * 128;    // [1024][128]
    __half* xpad = hp;                                    // scratch inside g_hp

    cudaFuncSetAttribute(h16_gemm_fused,
                         cudaFuncAttributeMaxDynamicSharedMemorySize, SM_BYTES);

    auto cdiv = [](int a, int b) { return (a + b - 1) / b; };
    const int MT = cdiv(NN, BMROWS);  // 196 m-tiles of 256 rows
    const int NB = cdiv(NN, 1024);    // 49 scan blocks

    // 0) init counters/sentinels + batched weight transpose (fp16) + pad x
    init_misc_kernel<<<cdiv(NN, 256), 256>>>(cnt, cur, gcnt, gmax);
    transpose_all_kernel<<<dim3(32, 4, 6), dim3(32, 8)>>>(
        W1, W2, lin_w, gW1, w1T, w2T, linT, gW1T);
    pad_x_kernel<<<cdiv(NN * 32, 256), 256>>>(x, xpad);

    // 1) node MLP via tensor cores (xpad -> hn -> h), all fp16 storage
    h16_gemm_fused<<<dim3(1, MT), GTHREADS, SM_BYTES>>>(
        xpad, NN, w1T, b1, hn, DD, 1, 1, nullptr, nullptr, nullptr, nullptr, nullptr);
    h16_gemm_fused<<<dim3(1, MT), GTHREADS, SM_BYTES>>>(
        hn, NN, w2T, b2, h, DD, 0, 1, nullptr, nullptr, nullptr, nullptr, nullptr);

    // 2) CSR by destination + batch offsets
    hist_kernel<<<cdiv(EE, 256), 256>>>(ei, cnt);
    scan_block_kernel<<<NB, 1024>>>(cnt, rowptr, bsum, NN);
    scan_bsum_kernel<<<1, 64>>>(bsum, NB);
    scan_add_kernel<<<cdiv(NN, 256), 256>>>(rowptr, bsum, NN);
    scatter_kernel<<<cdiv(EE, 256), 256>>>(ei, rowptr, cur, colA);
    batch_hist_kernel<<<cdiv(NN, 256), 256>>>(batch, gcnt);
    gscan_kernel<<<1, 1024>>>(gcnt, goff);

    // 3) GAT layers (gmax bound fused into GEMM epilogue)
    __half* hin = h;
    __half* hout = hn;
    for (int l = 0; l < LL; l++) {
        h16_gemm_fused<<<dim3(HH, MT), GTHREADS, SM_BYTES>>>(
            hin, NN, linT + (size_t)l * 512 * 128, nullptr, hp, HH * DD, 0, 1,
            att_src + l * HH * DD, att_dst + l * HH * DD, as_, ad_, gmax + l * HH);
        gat_aggregate_kernel<<<cdiv(NN, AGG_WARPS), AGG_WARPS * 32>>>(
            hp, as_, ad_, rowptr, colA, gmax + l * HH, conv_b + l * DD, hout);
        __half* t = hin; hin = hout; hout = t;
    }

    // 4) global mean pool (atomic-free; batch is sorted)
    pool_kernel<<<GG, DD>>>(hin, goff, pooled);

    // 5) FC head: FC1 on tensor cores (fp32 out), FC2 (K=1024) SIMT
    h16_gemm_fused<<<dim3(8, cdiv(GG, BMROWS)), GTHREADS, SM_BYTES>>>(
        pooled, GG, gW1T, gb1, hidden, HID, 1, 0, nullptr, nullptr, nullptr, nullptr,
        nullptr);
    sgemm_kernel<64, 64, 8, 4, 4><<<dim3(cdiv(DD, 64), cdiv(GG, 64)), 256>>>(
        hidden, gW2, gb2, out, GG, DD, HID, 0);
}

// round 17
// speedup vs baseline: 1.1701x; 1.0471x over previous
#include <cuda_runtime.h>
#include <cuda_fp16.h>
#include <cstdint>

#define NN 50000
#define EE 800000
#define GG 1024
#define DD 128
#define HH 4
#define LL 3
#define NODE_DIM 78
#define HID 1024

// ---------------- scratch (device globals; no allocation allowed) ----------
__device__ __half g_h[NN * DD];
__device__ __half g_hp[(size_t)NN * HH * DD];   // 51.2 MB; front also x-pad scratch
__device__ __half g_hn[NN * DD];
__device__ float g_as[NN * HH];
__device__ float g_ad[NN * HH];
__device__ int   g_rowptr[NN + 1];
__device__ int   g_cnt[NN];
__device__ int   g_cur[NN];
__device__ int   g_col[EE];
__device__ int   g_bsum[64];
__device__ int   g_gmax[LL * HH];
__device__ __half g_pooled[GG * DD];
__device__ int   g_gcnt[GG];
__device__ int   g_goff[GG + 1];
__device__ float g_hidden[GG * HID];
// transposed / K-padded fp16 weights: W1T, W2T, lin_wT[3][512][128], gW1T[1024][128]
__device__ __half g_wT[2 * 128 * 128 + 3 * 512 * 128 + 1024 * 128];

__device__ __forceinline__ int f2ord(float f) {
    int i = __float_as_int(f);
    return (i >= 0) ? i : i ^ 0x7FFFFFFF;
}
__device__ __forceinline__ float ord2f(int i) {
    return __int_as_float((i >= 0) ? i : i ^ 0x7FFFFFFF);
}
__device__ __forceinline__ float leaky02(float e) { return e > 0.f ? e : 0.2f * e; }

// ---------------- init: zero cnt/cur/gcnt, set gmax sentinels ---------------
__global__ void init_misc_kernel(int* cnt, int* cur, int* gcnt, int* gmax) {
    int i = blockIdx.x * blockDim.x + threadIdx.x;
    if (i < NN) { cnt[i] = 0; cur[i] = 0; }
    if (i < GG) gcnt[i] = 0;
    if (i < LL * HH) gmax[i] = f2ord(-3.0e38f);
}

// ---------------- pad x [NN,78] fp32 -> xp [NN,128] fp16 --------------------
__global__ void pad_x_kernel(const float* __restrict__ x, __half* __restrict__ xp) {
    int idx = blockIdx.x * blockDim.x + threadIdx.x;
    if (idx >= NN * 32) return;
    int row = idx >> 5;
    int q = idx & 31;
    int c = q * 4;
    const float* xr = x + (size_t)row * NODE_DIM;
    float4 v = make_float4(0.f, 0.f, 0.f, 0.f);
    if (c + 3 < NODE_DIM) {
        v.x = xr[c]; v.y = xr[c + 1]; v.z = xr[c + 2]; v.w = xr[c + 3];
    } else {
        if (c < NODE_DIM) v.x = xr[c];
        if (c + 1 < NODE_DIM) v.y = xr[c + 1];
        if (c + 2 < NODE_DIM) v.z = xr[c + 2];
        if (c + 3 < NODE_DIM) v.w = xr[c + 3];
    }
    __half2 p0 = __floats2half2_rn(v.x, v.y);
    __half2 p1 = __floats2half2_rn(v.z, v.w);
    uint2 u;
    u.x = *(uint32_t*)&p0;
    u.y = *(uint32_t*)&p1;
    *(uint2*)(xp + (size_t)row * 128 + c) = u;
}

// ---------------- batched transpose + pad-K of all 6 weights (fp16 out) -----
__global__ void transpose_all_kernel(const float* __restrict__ W1,
                                     const float* __restrict__ W2,
                                     const float* __restrict__ lin_w,
                                     const float* __restrict__ gW1,
                                     __half* __restrict__ w1T,
                                     __half* __restrict__ w2T,
                                     __half* __restrict__ linT,
                                     __half* __restrict__ gW1T) {
    __shared__ float t[32][33];
    const int job = blockIdx.z;
    const float* src; __half* dst; int K, Nsrc;
    switch (job) {
        case 0: src = W1; dst = w1T; K = NODE_DIM; Nsrc = 128; break;
        case 1: src = W2; dst = w2T; K = 128; Nsrc = 128; break;
        case 5: src = gW1; dst = gW1T; K = 128; Nsrc = 1024; break;
        default:
            src = lin_w + (size_t)(job - 2) * 128 * 512;
            dst = linT + (size_t)(job - 2) * 512 * 128;
            K = 128; Nsrc = 512; break;
    }
    int n0 = blockIdx.x * 32, k0 = blockIdx.y * 32;
    if (n0 >= Nsrc) return;
    int tx = threadIdx.x, ty = threadIdx.y;
#pragma unroll
    for (int i = 0; i < 32; i += 8) {
        int k = k0 + ty + i, n = n0 + tx;
        t[ty + i][tx] = (k < K && n < Nsrc) ? src[(size_t)k * Nsrc + n] : 0.f;
    }
    __syncthreads();
#pragma unroll
    for (int i = 0; i < 32; i += 8) {
        int n = n0 + ty + i, k = k0 + tx;
        if (n < Nsrc) dst[(size_t)n * 128 + k] = __float2half(t[tx][ty + i]);
    }
}

// ================= shared GEMM machinery (256x128 tile, 512 thr) ============
#define HS 136
#define BMROWS 256
#define GTHREADS 512
#define A_BYTES (BMROWS * HS * 2)
#define B_BYTES (128 * HS * 2)
#define ASBUF_OFF (A_BYTES + B_BYTES)
#define SM_BYTES (ASBUF_OFF + 2 * BMROWS * 4)

#define MMA_FRAGS_AND_LOOP(ACC)                                                  \
    _Pragma("unroll")                                                            \
    for (int ks = 0; ks < 8; ks++) {                                             \
        const int k0 = ks * 16;                                                  \
        uint32_t a[2][4];                                                        \
        _Pragma("unroll")                                                        \
        for (int mi = 0; mi < 2; mi++) {                                         \
            int rb = wm * 32 + mi * 16 + grp;                                    \
            a[mi][0] = *(const uint32_t*)(As + rb * HS + k0 + 2 * tig);          \
            a[mi][1] = *(const uint32_t*)(As + (rb + 8) * HS + k0 + 2 * tig);    \
            a[mi][2] = *(const uint32_t*)(As + rb * HS + k0 + 2 * tig + 8);      \
            a[mi][3] = *(const uint32_t*)(As + (rb + 8) * HS + k0 + 2 * tig + 8);\
        }                                                                        \
        uint32_t b[8][2];                                                        \
        _Pragma("unroll")                                                        \
        for (int ni = 0; ni < 8; ni++) {                                         \
            int cb = wn * 64 + ni * 8 + grp;                                     \
            b[ni][0] = *(const uint32_t*)(Bs + cb * HS + k0 + 2 * tig);          \
            b[ni][1] = *(const uint32_t*)(Bs + cb * HS + k0 + 2 * tig + 8);      \
        }                                                                        \
        _Pragma("unroll")                                                        \
        for (int mi = 0; mi < 2; mi++)                                           \
            _Pragma("unroll")                                                    \
            for (int ni = 0; ni < 8; ni++) {                                     \
                asm volatile(                                                    \
                    "mma.sync.aligned.m16n8k16.row.col.f32.f16.f16.f32 "         \
                    "{%0,%1,%2,%3}, {%4,%5,%6,%7}, {%8,%9}, {%0,%1,%2,%3};"      \
                    : "+f"(ACC[mi][ni][0]), "+f"(ACC[mi][ni][1]),                \
                      "+f"(ACC[mi][ni][2]), "+f"(ACC[mi][ni][3])                 \
                    : "r"(a[mi][0]), "r"(a[mi][1]), "r"(a[mi][2]), "r"(a[mi][3]),\
                      "r"(b[ni][0]), "r"(b[ni][1]));                             \
            }                                                                    \
    }

// ---------------- fused node-MLP: h = (relu(x@W1+b1))@W2 + b2 ---------------
__global__ void __launch_bounds__(GTHREADS)
mlp_fused_kernel(const __half* __restrict__ xp, int M,
                 const __half* __restrict__ w1T, const float* __restrict__ b1,
                 const __half* __restrict__ w2T, const float* __restrict__ b2,
                 __half* __restrict__ hOut)
{
    extern __shared__ char smc[];
    __half* As = (__half*)smc;
    __half* Bs = (__half*)(smc + A_BYTES);

    const int tid = threadIdx.x;
    const int wid = tid >> 5, lane = tid & 31;
    const int grp = lane >> 2, tig = lane & 3;
    const int wm = wid & 7, wn = wid >> 3;
    const int m0 = blockIdx.y * BMROWS;
    const int rows = min(BMROWS, M - m0);

    // load x tile + W1T
    {
        const uint4* src = (const uint4*)(xp + (size_t)m0 * 128);
        for (int idx = tid; idx < BMROWS * 16; idx += GTHREADS) {
            int row = idx >> 4, q = idx & 15;
            uint4 u = make_uint4(0u, 0u, 0u, 0u);
            if (row < rows) u = src[row * 16 + q];
            *(uint4*)(As + row * HS + q * 8) = u;
        }
        const uint4* srcb = (const uint4*)w1T;
        for (int idx = tid; idx < 128 * 16; idx += GTHREADS) {
            int row = idx >> 4, q = idx & 15;
            *(uint4*)(Bs + row * HS + q * 8) = srcb[row * 16 + q];
        }
    }
    __syncthreads();

    float acc[2][8][4];
#pragma unroll
    for (int mi = 0; mi < 2; mi++)
#pragma unroll
        for (int ni = 0; ni < 8; ni++)
#pragma unroll
            for (int q = 0; q < 4; q++) acc[mi][ni][q] = 0.f;
    MMA_FRAGS_AND_LOOP(acc)
    __syncthreads();   // all reads of As/Bs done

    // relu(acc + b1) -> As (fp16), and load W2T -> Bs
#pragma unroll
    for (int mi = 0; mi < 2; mi++) {
        const int r0 = wm * 32 + mi * 16 + grp;
        const int r1 = r0 + 8;
#pragma unroll
        for (int ni = 0; ni < 8; ni++) {
            const int col = wn * 64 + ni * 8 + tig * 2;
            float b0 = b1[col], bb1 = b1[col + 1];
            float v0 = fmaxf(acc[mi][ni][0] + b0, 0.f);
            float v1 = fmaxf(acc[mi][ni][1] + bb1, 0.f);
            float v2 = fmaxf(acc[mi][ni][2] + b0, 0.f);
            float v3 = fmaxf(acc[mi][ni][3] + bb1, 0.f);
            *(__half2*)(As + r0 * HS + col) = __floats2half2_rn(v0, v1);
            *(__half2*)(As + r1 * HS + col) = __floats2half2_rn(v2, v3);
        }
    }
    {
        const uint4* srcb = (const uint4*)w2T;
        for (int idx = tid; idx < 128 * 16; idx += GTHREADS) {
            int row = idx >> 4, q = idx & 15;
            *(uint4*)(Bs + row * HS + q * 8) = srcb[row * 16 + q];
        }
    }
    __syncthreads();

#pragma unroll
    for (int mi = 0; mi < 2; mi++)
#pragma unroll
        for (int ni = 0; ni < 8; ni++)
#pragma unroll
            for (int q = 0; q < 4; q++) acc[mi][ni][q] = 0.f;
    MMA_FRAGS_AND_LOOP(acc)

    // epilogue: h = acc + b2 (fp16)
#pragma unroll
    for (int mi = 0; mi < 2; mi++) {
        const int r0 = wm * 32 + mi * 16 + grp;
        const int r1 = r0 + 8;
        const int gm0 = m0 + r0, gm1 = m0 + r1;
#pragma unroll
        for (int ni = 0; ni < 8; ni++) {
            const int col = wn * 64 + ni * 8 + tig * 2;
            float b0 = b2[col], bb1 = b2[col + 1];
            if (gm0 < M)
                *(__half2*)(hOut + (size_t)gm0 * DD + col) =
                    __floats2half2_rn(acc[mi][ni][0] + b0, acc[mi][ni][1] + bb1);
            if (gm1 < M)
                *(__half2*)(hOut + (size_t)gm1 * DD + col) =
                    __floats2half2_rn(acc[mi][ni][2] + b0, acc[mi][ni][3] + bb1);
        }
    }
}

// ---------------- general GEMM with n-chunk loop + fused epilogue -----------
__global__ void __launch_bounds__(GTHREADS)
h16_gemm_fused(const __half* __restrict__ A, int M,
               const __half* __restrict__ Bt,    // [nChunksTotal*128][128] fp16
               const float* __restrict__ bias,   // global-col indexed or null
               void* __restrict__ C, int c_stride,
               int relu, int half_out, int nloop,
               const float* __restrict__ attS,   // global-col indexed or null
               const float* __restrict__ attD,
               float* __restrict__ asOut, float* __restrict__ adOut,
               int* __restrict__ gmaxOut)
{
    extern __shared__ char smc[];
    __half* As = (__half*)smc;
    __half* Bs = (__half*)(smc + A_BYTES);
    float* asbuf = (float*)(smc + ASBUF_OFF);
    float* adbuf = asbuf + BMROWS;

    const int tid = threadIdx.x;
    const int wid = tid >> 5, lane = tid & 31;
    const int grp = lane >> 2, tig = lane & 3;
    const int wm = wid & 7, wn = wid >> 3;
    const int m0 = blockIdx.y * BMROWS;
    const int rows = min(BMROWS, M - m0);

    // load A tile once
    {
        const uint4* src = (const uint4*)(A + (size_t)m0 * 128);
        for (int idx = tid; idx < BMROWS * 16; idx += GTHREADS) {
            int row = idx >> 4, q = idx & 15;
            uint4 u = make_uint4(0u, 0u, 0u, 0u);
            if (row < rows) u = src[row * 16 + q];
            *(uint4*)(As + row * HS + q * 8) = u;
        }
    }

    for (int j = 0; j < nloop; j++) {
        const int nc = blockIdx.x * nloop + j;
        const int colg0 = nc * 128;
        if (j > 0) __syncthreads();   // protect Bs/asbuf from previous chunk
        {
            const uint4* src = (const uint4*)(Bt + (size_t)nc * 128 * 128);
            for (int idx = tid; idx < 128 * 16; idx += GTHREADS) {
                int row = idx >> 4, q = idx & 15;
                *(uint4*)(Bs + row * HS + q * 8) = src[row * 16 + q];
            }
        }
        if (tid < BMROWS) { asbuf[tid] = 0.f; adbuf[tid] = 0.f; }
        __syncthreads();

        float acc[2][8][4];
#pragma unroll
        for (int mi = 0; mi < 2; mi++)
#pragma unroll
            for (int ni = 0; ni < 8; ni++)
#pragma unroll
                for (int q = 0; q < 4; q++) acc[mi][ni][q] = 0.f;
        MMA_FRAGS_AND_LOOP(acc)

#pragma unroll
        for (int mi = 0; mi < 2; mi++) {
            const int r0 = wm * 32 + mi * 16 + grp;
            const int r1 = r0 + 8;
            const int gm0 = m0 + r0, gm1 = m0 + r1;
            float aS0 = 0.f, aD0 = 0.f, aS1 = 0.f, aD1 = 0.f;
#pragma unroll
            for (int ni = 0; ni < 8; ni++) {
                const int col = wn * 64 + ni * 8 + tig * 2;
                const int cg = colg0 + col;
                float v0 = acc[mi][ni][0], v1 = acc[mi][ni][1];
                float v2 = acc[mi][ni][2], v3 = acc[mi][ni][3];
                if (bias) {
                    float b0 = bias[cg], b1 = bias[cg + 1];
                    v0 += b0; v1 += b1; v2 += b0; v3 += b1;
                }
                if (relu) {
                    v0 = fmaxf(v0, 0.f); v1 = fmaxf(v1, 0.f);
                    v2 = fmaxf(v2, 0.f); v3 = fmaxf(v3, 0.f);
                }
                if (attS) {
                    float s0 = attS[cg], s1 = attS[cg + 1];
                    float d0 = attD[cg], d1 = attD[cg + 1];
                    aS0 += v0 * s0 + v1 * s1;
                    aD0 += v0 * d0 + v1 * d1;
                    aS1 += v2 * s0 + v3 * s1;
                    aD1 += v2 * d0 + v3 * d1;
                }
                if (half_out) {
                    __half* Ch = (__half*)C;
                    if (gm0 < M)
                        *(__half2*)(Ch + (size_t)gm0 * c_stride + cg) =
                            __floats2half2_rn(v0, v1);
                    if (gm1 < M)
                        *(__half2*)(Ch + (size_t)gm1 * c_stride + cg) =
                            __floats2half2_rn(v2, v3);
                } else {
                    float* Cf = (float*)C;
                    if (gm0 < M)
                        *(float2*)(Cf + (size_t)gm0 * c_stride + cg) = make_float2(v0, v1);
                    if (gm1 < M)
                        *(float2*)(Cf + (size_t)gm1 * c_stride + cg) = make_float2(v2, v3);
                }
            }
            if (attS) {
#pragma unroll
                for (int off = 1; off < 4; off <<= 1) {
                    aS0 += __shfl_xor_sync(0xffffffffu, aS0, off);
                    aD0 += __shfl_xor_sync(0xffffffffu, aD0, off);
                    aS1 += __shfl_xor_sync(0xffffffffu, aS1, off);
                    aD1 += __shfl_xor_sync(0xffffffffu, aD1, off);
                }
                if (tig == 0) {
                    atomicAdd(&asbuf[r0], aS0);
                    atomicAdd(&adbuf[r0], aD0);
                    atomicAdd(&asbuf[r1], aS1);
                    atomicAdd(&adbuf[r1], aD1);
                }
            }
        }
        if (attS) {
            __syncthreads();
            if (tid < BMROWS && m0 + tid < M) {
                asOut[(m0 + tid) * HH + nc] = asbuf[tid];
                adOut[(m0 + tid) * HH + nc] = adbuf[tid];
            }
            if (wid == 15) {
                float m = -3.0e38f;
                for (int i = lane; i < rows; i += 32) m = fmaxf(m, asbuf[i]);
#pragma unroll
                for (int off = 16; off; off >>= 1)
                    m = fmaxf(m, __shfl_xor_sync(0xffffffffu, m, off));
                if (lane == 0) atomicMax(gmaxOut + nc, f2ord(m));
            }
        }
    }
}

// ---------------- SIMT SGEMM (FC2 only: K=1024) ------------------------------
template <int BM, int BN, int BK, int TM, int TN>
__global__ void __launch_bounds__((BM / TM) * (BN / TN))
sgemm_kernel(const float* __restrict__ A, const float* __restrict__ B,
             const float* __restrict__ bias, float* __restrict__ C,
             int M, int N, int K, int relu)
{
    constexpr int TX = BN / TN;
    constexpr int TY = BM / TM;
    constexpr int THREADS = TX * TY;
    __shared__ float As[BK][BM];
    __shared__ float Bs[BK][BN];

    const int tid = threadIdx.x;
    const int tx = tid % TX;
    const int ty = tid / TX;
    const int row0 = blockIdx.y * BM;
    const int col0 = blockIdx.x * BN;

    float acc[TM][TN];
#pragma unroll
    for (int i = 0; i < TM; i++)
#pragma unroll
        for (int j = 0; j < TN; j++) acc[i][j] = 0.f;

    for (int k0 = 0; k0 < K; k0 += BK) {
        for (int i = tid; i < BM * BK; i += THREADS) {
            int m = i / BK, k = i % BK;
            int gm = row0 + m, gk = k0 + k;
            As[k][m] = (gm < M && gk < K) ? A[(size_t)gm * K + gk] : 0.f;
        }
        for (int i = tid; i < BK * BN; i += THREADS) {
            int k = i / BN, nn = i % BN;
            int gn = col0 + nn, gk = k0 + k;
            Bs[k][nn] = (gn < N && gk < K) ? B[(size_t)gk * N + gn] : 0.f;
        }
        __syncthreads();
#pragma unroll
        for (int k = 0; k < BK; k++) {
            float ra[TM], rb[TN];
#pragma unroll
            for (int i = 0; i < TM; i++) ra[i] = As[k][ty * TM + i];
#pragma unroll
            for (int j = 0; j < TN; j++) rb[j] = Bs[k][tx * TN + j];
#pragma unroll
            for (int i = 0; i < TM; i++)
#pragma unroll
                for (int j = 0; j < TN; j++) acc[i][j] += ra[i] * rb[j];
        }
        __syncthreads();
    }

#pragma unroll
    for (int i = 0; i < TM; i++) {
        int gm = row0 + ty * TM + i;
        if (gm >= M) continue;
#pragma unroll
        for (int j = 0; j < TN; j++) {
            int gn = col0 + tx * TN + j;
            if (gn >= N) continue;
            float v = acc[i][j];
            if (bias) v += bias[gn];
            if (relu) v = fmaxf(v, 0.f);
            C[(size_t)gm * N + gn] = v;
        }
    }
}

// ---------------- CSR build (edge_index is int32) ---------------------------
__global__ void hist2_kernel(const int* __restrict__ ei, int* __restrict__ cnt,
                             const int* __restrict__ batch, int* __restrict__ gcnt) {
    int e = blockIdx.x * blockDim.x + threadIdx.x;
    if (e < EE) atomicAdd(&cnt[ei[EE + e]], 1);
    if (e < NN) atomicAdd(&gcnt[batch[e]], 1);
}

__global__ void scan_block_kernel(const int* __restrict__ cnt, int* __restrict__ rowptr,
                                  int* __restrict__ bsum, int n) {
    __shared__ int sh[1024];
    const int tid = threadIdx.x;
    const int i = blockIdx.x * 1024 + tid;
    sh[tid] = (i < n) ? cnt[i] : 0;
    __syncthreads();
    for (int off = 1; off < 1024; off <<= 1) {
        int t = (tid >= off) ? sh[tid - off] : 0;
        __syncthreads();
        sh[tid] += t;
        __syncthreads();
    }
    if (i < n) rowptr[i + 1] = sh[tid];
    if (tid == 1023) bsum[blockIdx.x] = sh[1023];
}
__global__ void scan_bsum_kernel(int* __restrict__ bsum, int nb) {
    __shared__ int sh[64];
    const int tid = threadIdx.x;
    sh[tid] = (tid < nb) ? bsum[tid] : 0;
    __syncthreads();
    for (int off = 1; off < 64; off <<= 1) {
        int t = (tid >= off) ? sh[tid - off] : 0;
        __syncthreads();
        sh[tid] += t;
        __syncthreads();
    }
    if (tid < nb) bsum[tid] = (tid == 0) ? 0 : sh[tid - 1];
}
__global__ void scan_add_kernel(int* __restrict__ rowptr, const int* __restrict__ bsum,
                                int n) {
    int i = blockIdx.x * blockDim.x + threadIdx.x;
    if (i == 0) rowptr[0] = 0;
    if (i < n) rowptr[i + 1] += bsum[i >> 10];
}

__global__ void scatter_kernel(const int* __restrict__ ei,
                               const int* __restrict__ rowptr,
                               int* __restrict__ cur, int* __restrict__ colA) {
    int e = blockIdx.x * blockDim.x + threadIdx.x;
    if (e < EE) {
        int d = ei[EE + e];
        int pos = atomicAdd(&cur[d], 1);
        colA[rowptr[d] + pos] = ei[e];
    }
}

// ---------------- GAT aggregation: warp-per-node, no block syncs ------------
#define AGG_WARPS 8
__global__ void __launch_bounds__(AGG_WARPS * 32)
gat_aggregate_kernel(const __half* __restrict__ hp,
                     const float* __restrict__ as_,
                     const float* __restrict__ ad_,
                     const int* __restrict__ rowptr,
                     const int* __restrict__ col,
                     const int* __restrict__ gmax,
                     const float* __restrict__ bias,
                     __half* __restrict__ hout) {
    const int warp = threadIdx.x >> 5, lane = threadIdx.x & 31;
    const int n = blockIdx.x * AGG_WARPS + warp;
    if (n >= NN) return;
    const int start = rowptr[n];
    const int deg = rowptr[n + 1] - start;
    const int total = deg + 1;

    const float4 ad4 = *(const float4*)(ad_ + n * HH);
    float4 mh;
    mh.x = leaky02(ord2f(gmax[0]) + ad4.x);
    mh.y = leaky02(ord2f(gmax[1]) + ad4.y);
    mh.z = leaky02(ord2f(gmax[2]) + ad4.z);
    mh.w = leaky02(ord2f(gmax[3]) + ad4.w);

    __shared__ float4 wsm[AGG_WARPS][32];
    __shared__ int    ssm[AGG_WARPS][32];

    const int hoff = lane * 8;
    float acc0[8], acc1[8];
#pragma unroll
    for (int k = 0; k < 8; k++) { acc0[k] = 0.f; acc1[k] = 0.f; }
    float4 dl = make_float4(0.f, 0.f, 0.f, 0.f);

    for (int base = 0; base < total; base += 32) {
        const int cnt = min(32, total - base);
        if (lane < cnt) {
            const int i = base + lane;
            const int s = (i < deg) ? col[start + i] : n;
            const float4 a4 = *(const float4*)(as_ + s * HH);
            float4 w4;
            w4.x = __expf(leaky02(a4.x + ad4.x) - mh.x);
            w4.y = __expf(leaky02(a4.y + ad4.y) - mh.y);
            w4.z = __expf(leaky02(a4.z + ad4.z) - mh.z);
            w4.w = __expf(leaky02(a4.w + ad4.w) - mh.w);
            dl.x += w4.x; dl.y += w4.y; dl.z += w4.z; dl.w += w4.w;
            wsm[warp][lane] = w4;
            ssm[warp][lane] = s;
        }
        __syncwarp();
#pragma unroll 2
        for (int j = 0; j < cnt; j++) {
            const int sj = ssm[warp][j];
            const float4 w4 = wsm[warp][j];
            const float wa = (lane & 16) ? w4.y : w4.x;
            const float wb = (lane & 16) ? w4.w : w4.z;
            const uint4 u0 = *(const uint4*)(hp + (size_t)sj * (HH * DD) + hoff);
            const uint4 u1 = *(const uint4*)(hp + (size_t)sj * (HH * DD) + 256 + hoff);
            const __half2* p0 = (const __half2*)&u0;
            const __half2* p1 = (const __half2*)&u1;
#pragma unroll
            for (int k = 0; k < 4; k++) {
                const float2 f0 = __half22float2(p0[k]);
                const float2 f1 = __half22float2(p1[k]);
                acc0[2 * k]     += wa * f0.x;
                acc0[2 * k + 1] += wa * f0.y;
                acc1[2 * k]     += wb * f1.x;
                acc1[2 * k + 1] += wb * f1.y;
            }
        }
        __syncwarp();
    }

#pragma unroll
    for (int off = 16; off; off >>= 1) {
        dl.x += __shfl_xor_sync(0xffffffffu, dl.x, off);
        dl.y += __shfl_xor_sync(0xffffffffu, dl.y, off);
        dl.z += __shfl_xor_sync(0xffffffffu, dl.z, off);
        dl.w += __shfl_xor_sync(0xffffffffu, dl.w, off);
    }
    const float da = 1.f / (((lane & 16) ? dl.y : dl.x) + 1e-16f);
    const float db = 1.f / (((lane & 16) ? dl.w : dl.z) + 1e-16f);

    float outv[8];
#pragma unroll
    for (int k = 0; k < 8; k++) {
        float part = acc0[k] * da + acc1[k] * db;
        part += __shfl_xor_sync(0xffffffffu, part, 16);
        outv[k] = 0.25f * part;
    }
    if (lane < 16) {
        const int c = lane * 8;
        float4 b0 = *(const float4*)(bias + c);
        float4 b1 = *(const float4*)(bias + c + 4);
        __half2 h0 = __floats2half2_rn(outv[0] + b0.x, outv[1] + b0.y);
        __half2 h1 = __floats2half2_rn(outv[2] + b0.z, outv[3] + b0.w);
        __half2 h2 = __floats2half2_rn(outv[4] + b1.x, outv[5] + b1.y);
        __half2 h3 = __floats2half2_rn(outv[6] + b1.z, outv[7] + b1.w);
        uint4 u;
        u.x = *(uint32_t*)&h0; u.y = *(uint32_t*)&h1;
        u.z = *(uint32_t*)&h2; u.w = *(uint32_t*)&h3;
        *(uint4*)(hout + (size_t)n * DD + c) = u;
    }
}

// ---------------- pooling (sorted batch -> contiguous ranges) ---------------
__global__ void gscan_kernel(const int* __restrict__ gcnt, int* __restrict__ goff) {
    __shared__ int sh[GG];
    const int tid = threadIdx.x;
    sh[tid] = gcnt[tid];
    __syncthreads();
    for (int off = 1; off < GG; off <<= 1) {
        int t = (tid >= off) ? sh[tid - off] : 0;
        __syncthreads();
        sh[tid] += t;
        __syncthreads();
    }
    if (tid == 0) goff[0] = 0;
    goff[tid + 1] = sh[tid];
}
__global__ void pool_kernel(const __half* __restrict__ hin,
                            const int* __restrict__ goff,
                            __half* __restrict__ pooled) {
    int g = blockIdx.x;
    int c = threadIdx.x;
    int s = goff[g], e = goff[g + 1];
    float acc = 0.f;
    for (int i = s; i < e; i++) acc += __half2float(hin[(size_t)i * DD + c]);
    pooled[g * DD + c] = __float2half(acc / fmaxf((float)(e - s), 1.f));
}

// ---------------- launch ----------------------------------------------------
extern "C" void kernel_launch(void* const* d_in, const int* in_sizes, int n_in,
                              void* d_out, int out_size) {
    const float* x       = (const float*)d_in[0];
    const int*   ei      = (const int*)d_in[1];
    const int*   batch   = (const int*)d_in[2];
    const float* W1      = (const float*)d_in[3];
    const float* b1      = (const float*)d_in[4];
    const float* W2      = (const float*)d_in[5];
    const float* b2      = (const float*)d_in[6];
    const float* lin_w   = (const float*)d_in[7];
    const float* att_src = (const float*)d_in[8];
    const float* att_dst = (const float*)d_in[9];
    const float* conv_b  = (const float*)d_in[10];
    const float* gW1     = (const float*)d_in[11];
    const float* gb1     = (const float*)d_in[12];
    const float* gW2     = (const float*)d_in[13];
    const float* gb2     = (const float*)d_in[14];
    float*       out     = (float*)d_out;

    float *as_, *ad_, *hidden;
    __half *h, *hn, *hp, *pooled, *wT;
    int *rowptr, *cnt, *cur, *colA, *gcnt, *goff, *bsum, *gmax;
    cudaGetSymbolAddress((void**)&h, g_h);
    cudaGetSymbolAddress((void**)&hp, g_hp);
    cudaGetSymbolAddress((void**)&hn, g_hn);
    cudaGetSymbolAddress((void**)&as_, g_as);
    cudaGetSymbolAddress((void**)&ad_, g_ad);
    cudaGetSymbolAddress((void**)&rowptr, g_rowptr);
    cudaGetSymbolAddress((void**)&cnt, g_cnt);
    cudaGetSymbolAddress((void**)&cur, g_cur);
    cudaGetSymbolAddress((void**)&colA, g_col);
    cudaGetSymbolAddress((void**)&bsum, g_bsum);
    cudaGetSymbolAddress((void**)&gmax, g_gmax);
    cudaGetSymbolAddress((void**)&pooled, g_pooled);
    cudaGetSymbolAddress((void**)&gcnt, g_gcnt);
    cudaGetSymbolAddress((void**)&goff, g_goff);
    cudaGetSymbolAddress((void**)&hidden, g_hidden);
    cudaGetSymbolAddress((void**)&wT, g_wT);

    __half* w1T  = wT;                                    // [128][128]
    __half* w2T  = wT + 128 * 128;                        // [128][128]
    __half* linT = wT + 2 * 128 * 128;                    // [3][512][128]
    __half* gW1T = wT + 2 * 128 * 128 + 3 * 512 * 128;    // [1024][128]
    __half* xpad = hp;                                    // scratch inside g_hp

    cudaFuncSetAttribute(h16_gemm_fused,
                         cudaFuncAttributeMaxDynamicSharedMemorySize, SM_BYTES);
    cudaFuncSetAttribute(mlp_fused_kernel,
                         cudaFuncAttributeMaxDynamicSharedMemorySize, SM_BYTES);

    auto cdiv = [](int a, int b) { return (a + b - 1) / b; };
    const int MT = cdiv(NN, BMROWS);  // 196 m-tiles of 256 rows
    const int NB = cdiv(NN, 1024);    // 49 scan blocks

    // 0) init + transpose weights + pad x
    init_misc_kernel<<<cdiv(NN, 256), 256>>>(cnt, cur, gcnt, gmax);
    transpose_all_kernel<<<dim3(32, 4, 6), dim3(32, 8)>>>(
        W1, W2, lin_w, gW1, w1T, w2T, linT, gW1T);
    pad_x_kernel<<<cdiv(NN * 32, 256), 256>>>(x, xpad);

    // 1) fused node MLP (xpad -> h)
    mlp_fused_kernel<<<dim3(1, MT), GTHREADS, SM_BYTES>>>(
        xpad, NN, w1T, b1, w2T, b2, h);

    // 2) CSR by destination + batch offsets
    hist2_kernel<<<cdiv(EE, 256), 256>>>(ei, cnt, batch, gcnt);
    scan_block_kernel<<<NB, 1024>>>(cnt, rowptr, bsum, NN);
    scan_bsum_kernel<<<1, 64>>>(bsum, NB);
    scan_add_kernel<<<cdiv(NN, 256), 256>>>(rowptr, bsum, NN);
    scatter_kernel<<<cdiv(EE, 256), 256>>>(ei, rowptr, cur, colA);
    gscan_kernel<<<1, 1024>>>(gcnt, goff);

    // 3) GAT layers: projection (2 head-chunks per CTA) + aggregate
    __half* hin = h;
    __half* hout = hn;
    for (int l = 0; l < LL; l++) {
        h16_gemm_fused<<<dim3(2, MT), GTHREADS, SM_BYTES>>>(
            hin, NN, linT + (size_t)l * 512 * 128, nullptr, hp, HH * DD, 0, 1, 2,
            att_src + l * HH * DD, att_dst + l * HH * DD, as_, ad_, gmax + l * HH);
        gat_aggregate_kernel<<<cdiv(NN, AGG_WARPS), AGG_WARPS * 32>>>(
            hp, as_, ad_, rowptr, colA, gmax + l * HH, conv_b + l * DD, hout);
        __half* t = hin; hin = hout; hout = t;
    }

    // 4) global mean pool
    pool_kernel<<<GG, DD>>>(hin, goff, pooled);

    // 5) FC head
    h16_gemm_fused<<<dim3(8, cdiv(GG, BMROWS)), GTHREADS, SM_BYTES>>>(
        pooled, GG, gW1T, gb1, hidden, HID, 1, 0, 1, nullptr, nullptr, nullptr,
        nullptr, nullptr);
    sgemm_kernel<64, 64, 8, 4, 4><<<dim3(cdiv(DD, 64), cdiv(GG, 64)), 256>>>(
        hidden, gW2, gb2, out, GG, DD, HID, 0);
}